// round 3
// baseline (speedup 1.0000x reference)
#include <cuda_runtime.h>
#include <stdint.h>

#define BN 8
#define HN 480
#define WN 640
#define GN 368640
#define TOTAL (BN*GN)
#define NPIX (BN*HN*WN)

#define U0c 320.0f
#define V0c 240.0f
#define DCOS 0.867f
#define DXY 0.01f

#define BINS (1 << 19)      // key >> 13 : sign(0)+8 exp+10 mantissa bits
#define SHIFT 13
#define BPT (BINS / 1024)   // 512 bins per thread in k_select phase 1

// ---------------- device scratch (no allocations allowed) ----------------
static __device__ float2       g_zip[NPIX];   // (gt, pred) per pixel
static __device__ unsigned int g_cnt[BINS];
static __device__ double       g_sum[BINS];

// ---------------- K0: zero histograms ------------------------------------
__global__ void k_zero() {
    int i = blockIdx.x * blockDim.x + threadIdx.x;
    if (i < BINS) { g_cnt[i] = 0u; g_sum[i] = 0.0; }
}

// ---------------- Kz: interleave gt/pred so each gather is one sector ----
__global__ void k_zip(const float* __restrict__ gt, const float* __restrict__ pr) {
    int i = blockIdx.x * blockDim.x + threadIdx.x;
    if (i >= NPIX / 4) return;
    float4 a = __ldg(&((const float4*)gt)[i]);
    float4 b = __ldg(&((const float4*)pr)[i]);
    float2* o = &g_zip[i * 4];
    o[0] = make_float2(a.x, b.x);
    o[1] = make_float2(a.y, b.y);
    o[2] = make_float2(a.z, b.z);
    o[3] = make_float2(a.w, b.w);
}

// ---------------- K1: main compute, one thread per (b, g) ----------------
__global__ void k_main(const int* __restrict__ p1x, const int* __restrict__ p1y,
                       const int* __restrict__ p2x, const int* __restrict__ p2y,
                       const int* __restrict__ p3x, const int* __restrict__ p3y) {
    int g = blockIdx.x * blockDim.x + threadIdx.x;
    if (g >= GN) return;
    int b = blockIdx.y;

    int x1 = __ldg(&p1x[g]), y1 = __ldg(&p1y[g]);
    int x2 = __ldg(&p2x[g]), y2 = __ldg(&p2y[g]);
    int x3 = __ldg(&p3x[g]), y3 = __ldg(&p3y[g]);
    const float2* zb = &g_zip[b * HN * WN];
    float2 z1 = __ldg(&zb[y1 * WN + x1]);
    float2 z2 = __ldg(&zb[y2 * WN + x2]);
    float2 z3 = __ldg(&zb[y3 * WN + x3]);

    float u1 = (float)x1 - U0c, vv1 = (float)y1 - V0c;
    float u2 = (float)x2 - U0c, vv2 = (float)y2 - V0c;
    float u3 = (float)x3 - U0c, vv3 = (float)y3 - V0c;
    const float rfx = 1.0f / 519.0f, rfy = 1.0f / 519.0f;

    // --- gt point cloud points ---
    float a1 = fabsf(z1.x), a2 = fabsf(z2.x), a3 = fabsf(z3.x);
    float P1x = u1 * a1 * rfx, P1y = vv1 * a1 * rfy, P1z = z1.x;
    float P2x = u2 * a2 * rfx, P2y = vv2 * a2 * rfy, P2z = z2.x;
    float P3x = u3 * a3 * rfx, P3y = vv3 * a3 * rfy, P3z = z3.x;

    // D vectors: d12, d13, d23
    float v0x = P2x - P1x, v0y = P2y - P1y, v0z = P2z - P1z;
    float w1x = P3x - P1x, w1y = P3y - P1y, w1z = P3z - P1z;
    float w2x = P3x - P2x, w2y = P3y - P2y, w2z = P3z - P2z;

    float e00 = v0x*v0x + v0y*v0y + v0z*v0z;
    float e11 = w1x*w1x + w1y*w1y + w1z*w1z;
    float e22 = w2x*w2x + w2y*w2y + w2z*w2z;
    float e01 = v0x*w1x + v0y*w1y + v0z*w1z;
    float e02 = v0x*w2x + v0y*w2y + v0z*w2z;
    float e12 = w1x*w2x + w1y*w2y + w1z*w2z;
    float n0 = sqrtf(e00), n1 = sqrtf(e11), n2 = sqrtf(e22);

    int cnt = 0;
    cnt += (fabsf(e00 / (n0*n0 + 1e-8f)) > DCOS);
    cnt += (fabsf(e11 / (n1*n1 + 1e-8f)) > DCOS);
    cnt += (fabsf(e22 / (n2*n2 + 1e-8f)) > DCOS);
    cnt += 2 * (fabsf(e01 / (n0*n1 + 1e-8f)) > DCOS);
    cnt += 2 * (fabsf(e02 / (n0*n2 + 1e-8f)) > DCOS);
    cnt += 2 * (fabsf(e12 / (n1*n2 + 1e-8f)) > DCOS);
    bool mask_cos = cnt > 3;

    bool mx = (fabsf(v0x) < DXY) | (fabsf(w1x) < DXY) | (fabsf(w2x) < DXY);
    bool my = (fabsf(v0y) < DXY) | (fabsf(w1y) < DXY) | (fabsf(w2y) < DXY);
    bool mz = (fabsf(v0z) < DXY) | (fabsf(w1z) < DXY) | (fabsf(w2z) < DXY);
    bool maskf = !((mx && my && mz) || mask_cos);

    if (!maskf) return;

    // --- pred point cloud points ---
    float b1 = fabsf(z1.y), b2 = fabsf(z2.y), b3 = fabsf(z3.y);
    float Q1x = u1 * b1 * rfx, Q1y = vv1 * b1 * rfy, Q1z = z1.y;
    float Q2x = u2 * b2 * rfx, Q2y = vv2 * b2 * rfy, Q2z = z2.y;
    float Q3x = u3 * b3 * rfx, Q3y = vv3 * b3 * rfy, Q3z = z3.y;

    // Replicate reference's broadcast bug: point-p's z==0 masks COORDINATE p
    // of all three points (zmask evaluated on original values).
    bool zm0 = (Q1z == 0.0f), zm1 = (Q2z == 0.0f), zm2 = (Q3z == 0.0f);
    if (zm0) { Q1x = 1e-4f; Q2x = 1e-4f; Q3x = 1e-4f; }
    if (zm1) { Q1y = 1e-4f; Q2y = 1e-4f; Q3y = 1e-4f; }
    if (zm2) { Q1z = 1e-4f; Q2z = 1e-4f; Q3z = 1e-4f; }

    float ux = Q2x - Q1x, uy = Q2y - Q1y, uz = Q2z - Q1z;
    float wx = Q3x - Q1x, wy = Q3y - Q1y, wz = Q3z - Q1z;

    // cross products (no FMA contraction, to track the reference closely)
    float gnx = __fsub_rn(__fmul_rn(v0y, w1z), __fmul_rn(v0z, w1y));
    float gny = __fsub_rn(__fmul_rn(v0z, w1x), __fmul_rn(v0x, w1z));
    float gnz = __fsub_rn(__fmul_rn(v0x, w1y), __fmul_rn(v0y, w1x));
    float dnx = __fsub_rn(__fmul_rn(uy, wz), __fmul_rn(uz, wy));
    float dny = __fsub_rn(__fmul_rn(uz, wx), __fmul_rn(ux, wz));
    float dnz = __fsub_rn(__fmul_rn(ux, wy), __fmul_rn(uy, wx));

    float gnn = sqrtf(gnx*gnx + gny*gny + gnz*gnz);
    float dnn = sqrtf(dnx*dnx + dny*dny + dnz*dnz);
    if (gnn == 0.0f) gnn = 0.01f;
    if (dnn == 0.0f) dnn = 0.01f;
    float L = fabsf(gnx / gnn - dnx / dnn)
            + fabsf(gny / gnn - dny / dnn)
            + fabsf(gnz / gnn - dnz / dnn);

    unsigned int bin = __float_as_uint(L) >> SHIFT;
    atomicAdd(&g_cnt[bin], 1u);
    atomicAdd(&g_sum[bin], (double)L);
}

// ---------------- block scan helper (1024 threads) -----------------------
__device__ __forceinline__ void blockscan(unsigned int c, double s,
                                          unsigned int& exC, double& exS,
                                          unsigned int& totC, double& totS) {
    __shared__ unsigned int wc[32];
    __shared__ double       ws[32];
    __shared__ unsigned int stc;
    __shared__ double       sts;
    int lane = threadIdx.x & 31, wid = threadIdx.x >> 5;
    __syncthreads();   // protect shared reuse across calls

    unsigned int ci = c; double si = s;
    #pragma unroll
    for (int o = 1; o < 32; o <<= 1) {
        unsigned int cc = __shfl_up_sync(0xFFFFFFFFu, ci, o);
        double       ss = __shfl_up_sync(0xFFFFFFFFu, si, o);
        if (lane >= o) { ci += cc; si += ss; }
    }
    if (lane == 31) { wc[wid] = ci; ws[wid] = si; }
    __syncthreads();
    if (wid == 0) {
        unsigned int v = wc[lane]; double w = ws[lane];
        unsigned int vi = v; double wi = w;
        #pragma unroll
        for (int o = 1; o < 32; o <<= 1) {
            unsigned int cc = __shfl_up_sync(0xFFFFFFFFu, vi, o);
            double       ss = __shfl_up_sync(0xFFFFFFFFu, wi, o);
            if (lane >= o) { vi += cc; wi += ss; }
        }
        wc[lane] = vi - v;   // exclusive warp offset
        ws[lane] = wi - w;
        if (lane == 31) { stc = vi; sts = wi; }
    }
    __syncthreads();
    exC = (ci - c) + wc[wid];
    exS = (si - s) + ws[wid];
    totC = stc; totS = sts;
}

// ---------------- K2: fully parallel trimmed-mean selection --------------
__global__ void k_select(float* __restrict__ out) {
    int t = threadIdx.x;
    unsigned int c = 0; double s = 0.0;
    int base = t * BPT;
    #pragma unroll 8
    for (int i = 0; i < BPT; i++) { c += g_cnt[base + i]; s += g_sum[base + i]; }

    unsigned int exC, n; double exS, total;
    blockscan(c, s, exC, exS, n, total);

    unsigned int drop = n >> 2;
    unsigned int keep = n - drop;
    if (drop == 0) {
        if (t == 0) out[0] = (float)(total / (double)(keep ? keep : 1u));
        return;
    }

    __shared__ int          sh_owner;
    __shared__ unsigned int sh_exC;
    __shared__ double       sh_exS;
    if (exC < drop && drop <= exC + c) { sh_owner = t; sh_exC = exC; sh_exS = exS; }
    __syncthreads();

    // phase 2: cooperative scan of the owner's BPT bins
    int ob = sh_owner * BPT;
    unsigned int r = drop - sh_exC;
    double sbelow = sh_exS;
    unsigned int c2 = 0; double s2 = 0.0;
    if (t < BPT) { c2 = g_cnt[ob + t]; s2 = g_sum[ob + t]; }

    unsigned int exC2, n2; double exS2, tot2;
    blockscan(c2, s2, exC2, exS2, n2, tot2);

    if (t < BPT && exC2 < r && r <= exC2 + c2) {
        double avg = s2 / (double)c2;                       // in-bin mean
        double dropped = sbelow + exS2 + (double)(r - exC2) * avg;
        out[0] = (float)((total - dropped) / (double)keep);
    }
}

// ---------------- launch -------------------------------------------------
extern "C" void kernel_launch(void* const* d_in, const int* in_sizes, int n_in,
                              void* d_out, int out_size) {
    const float* gt  = (const float*)d_in[0];
    const float* pr  = (const float*)d_in[1];
    const int*   p1x = (const int*)d_in[2];
    const int*   p1y = (const int*)d_in[3];
    const int*   p2x = (const int*)d_in[4];
    const int*   p2y = (const int*)d_in[5];
    const int*   p3x = (const int*)d_in[6];
    const int*   p3y = (const int*)d_in[7];
    float* out = (float*)d_out;

    k_zero<<<BINS / 256, 256>>>();
    k_zip<<<(NPIX / 4 + 255) / 256, 256>>>(gt, pr);
    dim3 gmain(GN / 256, BN);
    k_main<<<gmain, 256>>>(p1x, p1y, p2x, p2y, p3x, p3y);
    k_select<<<1, 1024>>>(out);
}